// round 14
// baseline (speedup 1.0000x reference)
#include <cuda_runtime.h>
#include <stdint.h>
#include <stddef.h>

// Problem constants (fixed by setup_inputs)
#define B_   4
#define LQ_  1024
#define LK_  1024
#define DM_  512
#define NH_  8
#define DK_  64
#define BH_  (B_*NH_)   // 32
#define JT_  64         // j-tiles for vbar partials (16 j each)

// ---------------- scratch (device globals; tiny) ----------------
__device__ float   g_wn[BH_*LK_];                // softmax weights (normalized)
__device__ float   g_vbar_part[(size_t)JT_*BH_*DM_]; // partial weighted-V sums
__device__ float   g_y[B_*DM_];                  // concat-head V projection
__device__ float   g_cvec[B_*DM_];               // leaky(fc(y)+b): per-b constant
__device__ uint8_t g_rowflag[B_*LQ_];            // per (b,i): any mask set in row

// ---------------- host-side aux resources (created once, before any capture) ----------------
struct AuxRes {
    cudaStream_t s2;
    cudaEvent_t  e_fork, e_flag, e_score, e_tail;
    AuxRes() {
        cudaStreamCreateWithFlags(&s2, cudaStreamNonBlocking);
        cudaEventCreateWithFlags(&e_fork,  cudaEventDisableTiming);
        cudaEventCreateWithFlags(&e_flag,  cudaEventDisableTiming);
        cudaEventCreateWithFlags(&e_score, cudaEventDisableTiming);
        cudaEventCreateWithFlags(&e_tail,  cudaEventDisableTiming);
    }
};
static AuxRes g_aux;

// ---------------- small PTX helpers ----------------
__device__ __forceinline__ uint32_t smem_u32(const void* p) {
    uint32_t a;
    asm("{ .reg .u64 t; cvta.to.shared.u64 t, %1; cvt.u32.u64 %0, t; }"
        : "=r"(a) : "l"(p));
    return a;
}
__device__ __forceinline__ void bulk_store(void* g, uint32_t s, uint32_t bytes) {
    asm volatile("cp.async.bulk.global.shared::cta.bulk_group [%0], [%1], %2;"
                 :: "l"(g), "r"(s), "r"(bytes) : "memory");
}

// ---------------- K0: per-row mask flags (depends only on mask) ----------------
__global__ void k_rowflag(const uint8_t* __restrict__ mask) {
    int warp = threadIdx.x >> 5, lane = threadIdx.x & 31;
    int row  = blockIdx.x*8 + warp;              // 0..4095 (= b*1024 + i)
    const uint4* m = reinterpret_cast<const uint4*>(mask + (size_t)row*LK_);
    uint4 a = __ldg(&m[lane]);
    uint4 c = __ldg(&m[lane + 32]);
    uint32_t x = a.x|a.y|a.z|a.w|c.x|c.y|c.z|c.w;
    int any = __any_sync(0xffffffffu, x != 0u);
    if (lane == 0) g_rowflag[row] = (uint8_t)any;
}

// ---------------- K1 (fused): wk_eff fold -> sk -> softmax -> g_wn ----------------
// 32 blocks (one per (b,h)) x 512 threads (16 warps)
__global__ void k_score(const float* __restrict__ kin,
                        const float* __restrict__ Wk,
                        const float* __restrict__ wm) {
    __shared__ float s_wke[DM_];
    __shared__ float s_sk[LK_];
    __shared__ float warpred[16];
    __shared__ float bcast[2];
    int bh = blockIdx.x;
    int b  = bh >> 3, h = bh & 7;
    int t  = threadIdx.x;
    int warp = t >> 5, lane = t & 31;

    // folded key weight: wke[c] = sum_d wm_k[d] * Wk[h*64+d, c]
    {
        float acc = 0.f;
        #pragma unroll 8
        for (int d = 0; d < DK_; ++d)
            acc += __ldg(&wm[DK_ + d]) * __ldg(&Wk[(h*DK_ + d)*DM_ + t]);
        s_wke[t] = acc;
    }
    __syncthreads();

    // scores: each warp owns 64 consecutive j rows
    float wke[16];
    #pragma unroll
    for (int tt = 0; tt < 16; ++tt) wke[tt] = s_wke[lane + 32*tt];
    #pragma unroll 4
    for (int r = 0; r < 64; ++r) {
        int j = warp*64 + r;
        const float* kr = kin + ((size_t)b*LK_ + j)*DM_;
        float acc = 0.f;
        #pragma unroll
        for (int tt = 0; tt < 16; ++tt) acc += wke[tt] * __ldg(&kr[lane + 32*tt]);
        #pragma unroll
        for (int o = 16; o; o >>= 1) acc += __shfl_xor_sync(0xffffffffu, acc, o);
        if (lane == 0) s_sk[j] = acc;
    }
    __syncthreads();

    // softmax over 1024 scores (2 per thread)
    float v0 = s_sk[t], v1 = s_sk[t + 512];
    float m = fmaxf(v0, v1);
    #pragma unroll
    for (int o = 16; o; o >>= 1) m = fmaxf(m, __shfl_xor_sync(0xffffffffu, m, o));
    if (lane == 0) warpred[warp] = m;
    __syncthreads();
    if (t == 0) {
        float mm = warpred[0];
        #pragma unroll
        for (int i = 1; i < 16; ++i) mm = fmaxf(mm, warpred[i]);
        bcast[0] = mm;
    }
    __syncthreads();
    float mx = bcast[0];
    float e0 = expf(v0 - mx), e1 = expf(v1 - mx);
    float s = e0 + e1;
    #pragma unroll
    for (int o = 16; o; o >>= 1) s += __shfl_xor_sync(0xffffffffu, s, o);
    if (lane == 0) warpred[warp] = s;
    __syncthreads();
    if (t == 0) {
        float tot = 0.f;
        #pragma unroll
        for (int i = 0; i < 16; ++i) tot += warpred[i];
        bcast[1] = tot;
    }
    __syncthreads();
    float inv = 1.f / bcast[1];
    g_wn[bh*LK_ + t]       = e0*inv;
    g_wn[bh*LK_ + t + 512] = e1*inv;
}

// ---------------- K4: vbar partials (measured-best config) ----------------
// grid (4, 64 jt, 2 cc) x 256 threads; each block: 16 j rows, 256 cols, 8 heads
__global__ void k_vbar_part(const float* __restrict__ vin) {
    int b = blockIdx.x, jt = blockIdx.y, cc = blockIdx.z;
    int t = threadIdx.x;
    __shared__ float sw[NH_*16];
    if (t < NH_*16) {
        int h = t >> 4, jj = t & 15;
        sw[t] = g_wn[(b*NH_ + h)*LK_ + jt*16 + jj];
    }
    __syncthreads();
    int c = cc*256 + t;
    float acc[NH_];
    #pragma unroll
    for (int h = 0; h < NH_; ++h) acc[h] = 0.f;
    const float* vb = vin + ((size_t)b*LK_ + jt*16)*DM_ + c;
    #pragma unroll
    for (int j = 0; j < 16; ++j) {
        float vv = __ldg(vb + (size_t)j*DM_);
        #pragma unroll
        for (int h = 0; h < NH_; ++h) acc[h] += sw[h*16 + j] * vv;
    }
    #pragma unroll
    for (int h = 0; h < NH_; ++h)
        g_vbar_part[((size_t)jt*BH_ + b*NH_ + h)*DM_ + c] = acc[h];
}

// ---------------- K5: fused partial-reduce + y = Wv.vbar ----------------
// grid (4 b, 8 h) x 256 threads
__global__ void k_red_y(const float* __restrict__ Wv) {
    __shared__ float s_vbar[DM_];
    int b = blockIdx.x, h = blockIdx.y, t = threadIdx.x;
    float s0 = 0.f, s1 = 0.f;
    #pragma unroll 8
    for (int jt = 0; jt < JT_; ++jt) {
        const float* p = g_vbar_part + ((size_t)jt*BH_ + b*NH_ + h)*DM_;
        s0 += p[t]; s1 += p[t + 256];
    }
    s_vbar[t] = s0; s_vbar[t + 256] = s1;
    __syncthreads();
    int warp = t >> 5, lane = t & 31;
    #pragma unroll
    for (int i = 0; i < 8; ++i) {
        int hd = h*64 + i*8 + warp;
        const float* wr = Wv + (size_t)hd*DM_;
        float acc = 0.f;
        #pragma unroll
        for (int tt = 0; tt < 16; ++tt)
            acc += __ldg(&wr[lane + 32*tt]) * s_vbar[lane + 32*tt];
        #pragma unroll
        for (int o = 16; o; o >>= 1) acc += __shfl_xor_sync(0xffffffffu, acc, o);
        if (lane == 0) g_y[b*DM_ + hd] = acc;
    }
}

// ---------------- K6: cvec[b,m] = leaky(y[b,:] . fc_w[m,:] + fc_b[m]) ----------------
__global__ void k_cvec(const float* __restrict__ fc_w, const float* __restrict__ fc_b) {
    int b = blockIdx.x;                            // (4,64) x 256 threads
    int warp = threadIdx.x >> 5, lane = threadIdx.x & 31;
    int m = blockIdx.y*8 + warp;
    const float* wr = fc_w + (size_t)m*DM_;
    const float* yb = g_y + b*DM_;
    float acc = 0.f;
    #pragma unroll
    for (int t = 0; t < 16; ++t) acc += __ldg(&wr[lane + 32*t]) * yb[lane + 32*t];
    #pragma unroll
    for (int o = 16; o; o >>= 1) acc += __shfl_xor_sync(0xffffffffu, acc, o);
    if (lane == 0) {
        float v = acc + __ldg(&fc_b[m]);
        g_cvec[b*DM_ + m] = (v >= 0.f) ? v : 0.2f*v;
    }
}

// ---------------- K7: attn replication — single-wave deep-queue TMA writer ----------------
// 128 blocks x 512 threads; each block owns a 1MiB contiguous span (256 rows):
// stage 32KB once, issue 32 bulk stores back-to-back, single commit+wait.
__global__ void k_attn(const uint8_t* __restrict__ mask, float* __restrict__ attn) {
    int t = threadIdx.x;
    __shared__ __align__(16) float s_buf[8*LK_];   // 32 KiB: weight row x8
    __shared__ float sred[512];
    __shared__ uint32_t sflags[64];                // 256 row-flags
    int blk  = blockIdx.x;
    int page = blk >> 2;                // attn layout [h*B + b][i][j]
    int sub  = blk & 3;                 // 4 sub-spans of 256 rows
    int b    = page & 3, h = page >> 2;
    int bh   = b*NH_ + h;
    int rl   = t >> 8;                  // row-lane 0/1
    int col  = t & 255;
    float4 w = reinterpret_cast<const float4*>(g_wn + bh*LK_)[col];
    #pragma unroll
    for (int r = 0; r < 4; ++r)
        reinterpret_cast<float4*>(s_buf)[(r*2 + rl)*256 + col] = w;
    int i0 = sub*256;
    int anyv = 0;
    if (t < 64) {
        uint32_t v = reinterpret_cast<const uint32_t*>(g_rowflag)[b*256 + sub*64 + t];
        sflags[t] = v;
        anyv = (v != 0u);
    }
    int s_any = __syncthreads_or(anyv);
    float* rowbase = attn + (size_t)page*(LQ_*LK_) + (size_t)i0*LK_;
    if (!s_any) {
        // fast path: 32 async 32KB DMA copies, one commit, one terminal wait.
        // Single wave across SMs: drain fully overlaps issue everywhere.
        if (t == 0) {
            uint32_t ssrc = smem_u32(s_buf);
            asm volatile("fence.proxy.async.shared::cta;" ::: "memory");
            #pragma unroll
            for (int r = 0; r < 32; ++r)
                bulk_store(rowbase + (size_t)r*8*LK_, ssrc, 8*LK_*4);
            asm volatile("cp.async.bulk.commit_group;" ::: "memory");
            asm volatile("cp.async.bulk.wait_group 0;" ::: "memory");
        }
    } else {
        // exact masked renormalization per row (uniform control flow, STG path)
        #pragma unroll 1
        for (int it = 0; it < 128; ++it) {
            int ri = it*2 + rl;              // row within 256-row span
            int i  = i0 + ri;
            int myflag = (sflags[ri >> 2] >> ((ri & 3)*8)) & 0xff;
            const uint32_t* mrow = reinterpret_cast<const uint32_t*>(
                mask + ((size_t)b*LQ_ + i)*LK_);
            uint32_t m4 = myflag ? __ldg(&mrow[col]) : 0u;
            float corr = 0.f;
            if (m4 & 0x000000ffu) corr += w.x;
            if (m4 & 0x0000ff00u) corr += w.y;
            if (m4 & 0x00ff0000u) corr += w.z;
            if (m4 & 0xff000000u) corr += w.w;
            sred[t] = corr;
            __syncthreads();
            #pragma unroll
            for (int o = 128; o; o >>= 1) {
                if (col < o) sred[rl*256 + col] += sred[rl*256 + col + o];
                __syncthreads();
            }
            float denom = 1.f - sred[rl*256];
            __syncthreads();
            float4 ov;
            if (denom <= 1e-12f) {
                ov.x = ov.y = ov.z = ov.w = 1.f/(float)LK_;  // fully-masked: uniform
            } else {
                float inv = 1.f/denom;
                ov.x = (m4 & 0x000000ffu) ? 0.f : w.x*inv;
                ov.y = (m4 & 0x0000ff00u) ? 0.f : w.y*inv;
                ov.z = (m4 & 0x00ff0000u) ? 0.f : w.z*inv;
                ov.w = (m4 & 0xff000000u) ? 0.f : w.w*inv;
            }
            reinterpret_cast<float4*>(rowbase + (size_t)ri*LK_)[col] = ov;
        }
    }
}

// ---------------- K8: out[b,i,:] = LN(q[b,i,:] + cvec[b,:]) ----------------
// 256 blocks x 512 threads; 16 rows each (warp per row)
__global__ void k_ln(const float* __restrict__ q,
                     const float* __restrict__ ln_g,
                     const float* __restrict__ ln_b,
                     float* __restrict__ out) {
    __shared__ float sc[DM_], sg[DM_], sb[DM_];
    int t = threadIdx.x;
    int row0 = blockIdx.x*16;
    int b    = row0 >> 10;
    sc[t] = g_cvec[b*DM_ + t];
    sg[t] = __ldg(&ln_g[t]);
    sb[t] = __ldg(&ln_b[t]);
    __syncthreads();
    int warp = t >> 5, lane = t & 31;
    int row = row0 + warp;
    const float4* q4 = reinterpret_cast<const float4*>(q) + (size_t)row*128;
    float4 x[4];
    float s = 0.f, ss = 0.f;
    #pragma unroll
    for (int kk = 0; kk < 4; ++kk) {
        float4 qq = __ldg(&q4[lane + 32*kk]);
        int c = 4*(lane + 32*kk);
        x[kk].x = qq.x + sc[c+0];
        x[kk].y = qq.y + sc[c+1];
        x[kk].z = qq.z + sc[c+2];
        x[kk].w = qq.w + sc[c+3];
        s  += x[kk].x + x[kk].y + x[kk].z + x[kk].w;
        ss += x[kk].x*x[kk].x + x[kk].y*x[kk].y + x[kk].z*x[kk].z + x[kk].w*x[kk].w;
    }
    #pragma unroll
    for (int o = 16; o; o >>= 1) {
        s  += __shfl_xor_sync(0xffffffffu, s,  o);
        ss += __shfl_xor_sync(0xffffffffu, ss, o);
    }
    float mean = s * (1.f/512.f);
    float var  = ss * (1.f/512.f) - mean*mean;
    float inv  = rsqrtf(var + 1e-5f);
    float4* o4 = reinterpret_cast<float4*>(out) + (size_t)row*128;
    #pragma unroll
    for (int kk = 0; kk < 4; ++kk) {
        int c = 4*(lane + 32*kk);
        float4 ov;
        ov.x = (x[kk].x - mean)*inv*sg[c+0] + sb[c+0];
        ov.y = (x[kk].y - mean)*inv*sg[c+1] + sb[c+1];
        ov.z = (x[kk].z - mean)*inv*sg[c+2] + sb[c+2];
        ov.w = (x[kk].w - mean)*inv*sg[c+3] + sb[c+3];
        o4[lane + 32*kk] = ov;
    }
}

// ---------------- launch: fork-join two-stream graph ----------------
extern "C" void kernel_launch(void* const* d_in, const int* in_sizes, int n_in,
                              void* d_out, int out_size) {
    const float*   qin  = (const float*)d_in[0];
    const float*   kin  = (const float*)d_in[1];
    const float*   vin  = (const float*)d_in[2];
    const uint8_t* mask = (const uint8_t*)d_in[3];
    // d_in[4] = Wq (provably unused: softmax is shift-invariant per row)
    const float*   Wk   = (const float*)d_in[5];
    const float*   Wv   = (const float*)d_in[6];
    const float*   wm   = (const float*)d_in[7];
    const float*   fc_w = (const float*)d_in[8];
    const float*   fc_b = (const float*)d_in[9];
    const float*   ln_g = (const float*)d_in[10];
    const float*   ln_b = (const float*)d_in[11];

    float* out  = (float*)d_out;                       // [4,1024,512]
    float* attn = out + (size_t)B_*LQ_*DM_;            // [32,1024,1024]

    cudaStream_t s0 = 0;                               // harness capture stream (legacy)
    cudaStream_t s2 = g_aux.s2;

    // fork immediately: side stream computes row-flags concurrently with k_score
    cudaEventRecord(g_aux.e_fork, s0);
    cudaStreamWaitEvent(s2, g_aux.e_fork, 0);
    k_rowflag<<<512, 256, 0, s2>>>(mask);
    cudaEventRecord(g_aux.e_flag, s2);

    // main stream: fused score prefix
    k_score<<<BH_, 512, 0, s0>>>(kin, Wk, wm);
    cudaEventRecord(g_aux.e_score, s0);

    // side stream: small tail (needs g_wn)
    cudaStreamWaitEvent(s2, g_aux.e_score, 0);
    k_vbar_part<<<dim3(B_, JT_, 2), 256, 0, s2>>>(vin);
    k_red_y<<<dim3(B_, NH_), 256, 0, s2>>>(Wv);
    k_cvec<<<dim3(B_, DM_/8), 256, 0, s2>>>(fc_w, fc_b);
    k_ln<<<256, 512, 0, s2>>>(qin, ln_g, ln_b, out);
    cudaEventRecord(g_aux.e_tail, s2);

    // main stream: 128 MiB attn replication (single-wave deep-queue TMA writer)
    cudaStreamWaitEvent(s0, g_aux.e_flag, 0);
    k_attn<<<128, 512, 0, s0>>>(mask, attn);

    // join
    cudaStreamWaitEvent(s0, g_aux.e_tail, 0);
}